// round 14
// baseline (speedup 1.0000x reference)
#include <cuda_runtime.h>

#define B 8
#define N 8192
#define D_INF 13
#define M 2048
#define K 32
#define NC (B*M)          /* 16384 centers */
#define NPAIR (NC/2)      /* 8192 */

/* output layout (floats): x_out, pos_s, batch_s */
#define X_OFF   0
#define P_OFF   (NC*128)
#define BA_OFF  (P_OFF + NC*3)

/* scratch (device globals; no allocation allowed) */
static __device__ int   g_fps_idx[NC];
static __device__ int   g_nbr[NC*K];
static __device__ int   g_nvalid[NC];
static __device__ float g_px[B*N];
static __device__ float g_py[B*N];
static __device__ float g_pz[B*N];

/* ---------------- packed f32x2 helpers (per-lane IEEE RN, bit-exact) ---- */
union F2U { unsigned long long u; float2 f; };

__device__ __forceinline__ unsigned long long pk2(float lo, float hi) {
    F2U c; c.f = make_float2(lo, hi); return c.u;
}
__device__ __forceinline__ float2 up2(unsigned long long v) {
    F2U c; c.u = v; return c.f;
}
__device__ __forceinline__ unsigned long long add2(unsigned long long a,
                                                   unsigned long long b) {
    unsigned long long r;
    asm("add.rn.f32x2 %0, %1, %2;" : "=l"(r) : "l"(a), "l"(b));
    return r;
}
__device__ __forceinline__ unsigned long long mul2(unsigned long long a,
                                                   unsigned long long b) {
    unsigned long long r;
    asm("mul.rn.f32x2 %0, %1, %2;" : "=l"(r) : "l"(a), "l"(b));
    return r;
}

/* ---------------- cluster / mbarrier primitives ------------------------ */
__device__ __forceinline__ unsigned smem_u32(const void* p) {
    unsigned a;
    asm("{ .reg .u64 t; cvta.to.shared.u64 t, %1; cvt.u32.u64 %0, t; }"
        : "=r"(a) : "l"(p));
    return a;
}
__device__ __forceinline__ unsigned ctarank() {
    unsigned r; asm("mov.u32 %0, %%cluster_ctarank;" : "=r"(r)); return r;
}
__device__ __forceinline__ void mbar_init(unsigned addr, unsigned cnt) {
    asm volatile("mbarrier.init.shared.b64 [%0], %1;" :: "r"(addr), "r"(cnt)
                 : "memory");
}
__device__ __forceinline__ void st_cluster_u64(unsigned laddr, unsigned rank,
                                               unsigned long long v) {
    asm volatile(
        "{\n\t.reg .b32 ra;\n\t"
        "mapa.shared::cluster.u32 ra, %0, %1;\n\t"
        "st.shared::cluster.u64 [ra], %2;\n\t}"
        :: "r"(laddr), "r"(rank), "l"(v) : "memory");
}
__device__ __forceinline__ void mbar_arrive_cluster(unsigned laddr,
                                                    unsigned rank) {
    asm volatile(
        "{\n\t.reg .b32 ra;\n\t"
        "mapa.shared::cluster.u32 ra, %0, %1;\n\t"
        "mbarrier.arrive.release.cluster.shared::cluster.b64 _, [ra];\n\t}"
        :: "r"(laddr), "r"(rank) : "memory");
}
__device__ __forceinline__ void mbar_wait_cluster(unsigned addr, unsigned par) {
    asm volatile(
        "{\n\t.reg .pred P;\n\t"
        "W%=:\n\t"
        "mbarrier.try_wait.parity.acquire.cluster.shared::cta.b64 P, [%0], %1, 0x989680;\n\t"
        "@!P bra W%=;\n\t}"
        :: "r"(addr), "r"(par) : "memory");
}
__device__ __forceinline__ void cluster_sync_all() {
    asm volatile("barrier.cluster.arrive.aligned;" ::: "memory");
    asm volatile("barrier.cluster.wait.aligned;"   ::: "memory");
}

/* ------------------------------------------------------------------ */
/* AoS -> SoA transpose of pos                                        */
/* ------------------------------------------------------------------ */
__global__ void soa_kernel(const float* __restrict__ pos) {
    int i = blockIdx.x * blockDim.x + threadIdx.x;
    if (i < B*N) {
        g_px[i] = pos[3*i + 0];
        g_py[i] = pos[3*i + 1];
        g_pz[i] = pos[3*i + 2];
    }
}

/* ------------------------------------------------------------------ */
/* FPS v4: 4-CTA cluster per batch, 512 thr/CTA, 4 points/thread.     */
/* Per step: packed-exact distance update (bit-identical to jnp),     */
/* lane argmax (strict > keeps smallest idx), 64-bit key shfl-max,    */
/* 1 intra barrier, warp0 reduces 16 keys and pushes the CTA          */
/* candidate to all 4 CTAs (mapa+st.shared::cluster), arrives on all  */
/* 4 mbarriers (release.cluster). Everyone try_waits acquire.cluster, */
/* reads the 4 double-buffered slots, reduces -> `last`.              */
/* Key = (distBits<<32) | ~idx : max key == max dist, then min idx.   */
/* ------------------------------------------------------------------ */
#define FPS_CTAS 4
#define FPS_T 512
#define PPC (N/FPS_CTAS)      /* 2048 points per CTA */

__global__ void __launch_bounds__(FPS_T, 1) fps_kernel() {
    const int  b    = blockIdx.x >> 2;
    const int  rank = (int)ctarank();
    const int  t    = threadIdx.x;
    const int  w    = t >> 5;
    const int  lane = t & 31;
    const int  bN   = b*N;
    const int  n0   = rank*PPC + t;       /* this lane's first point */

    __shared__ unsigned long long skey[16];
    __shared__ unsigned long long slots[2][FPS_CTAS];
    __shared__ alignas(8) unsigned long long mbar;

    const unsigned slots_a = smem_u32(&slots[0][0]);
    const unsigned mbar_a  = smem_u32(&mbar);

    if (t == 0) mbar_init(mbar_a, FPS_CTAS);
    __syncthreads();
    cluster_sync_all();                   /* all mbarriers live before arrivals */

    /* 4 points/thread, packed in pairs (u0,u1) and (u2,u3) */
    unsigned long long X2[2], Y2[2], Z2[2];
    float D[4];
#pragma unroll
    for (int h = 0; h < 2; h++) {
        int p0 = bN + n0 + (2*h)*FPS_T, p1 = p0 + FPS_T;
        X2[h] = pk2(g_px[p0], g_px[p1]);
        Y2[h] = pk2(g_py[p0], g_py[p1]);
        Z2[h] = pk2(g_pz[p0], g_pz[p1]);
        D[2*h] = 1e10f; D[2*h+1] = 1e10f;
    }

    if (rank == 0 && t == 0) g_fps_idx[b*M] = 0;
    int last = 0;
    unsigned ph = 0;

    for (int s = 1; s < M; s++) {
        const int p = s & 1;
        const float lx = g_px[bN+last], ly = g_py[bN+last], lz = g_pz[bN+last];
        const unsigned long long nx = pk2(-lx, -lx);
        const unsigned long long ny = pk2(-ly, -ly);
        const unsigned long long nz = pk2(-lz, -lz);

#pragma unroll
        for (int h = 0; h < 2; h++) {
            unsigned long long dx = add2(X2[h], nx);
            unsigned long long dy = add2(Y2[h], ny);
            unsigned long long dz = add2(Z2[h], nz);
            /* match jnp: separate mul + left-to-right add, no FMA */
            unsigned long long d2 = add2(add2(mul2(dx,dx), mul2(dy,dy)),
                                         mul2(dz,dz));
            float2 dd = up2(d2);
            D[2*h]   = fminf(D[2*h],   dd.x);
            D[2*h+1] = fminf(D[2*h+1], dd.y);
        }

        /* lane argmax, strict > : first (smallest) index wins ties */
        float m = D[0]; int mi = n0;
        if (D[1] > m) { m = D[1]; mi = n0 + FPS_T; }
        if (D[2] > m) { m = D[2]; mi = n0 + 2*FPS_T; }
        if (D[3] > m) { m = D[3]; mi = n0 + 3*FPS_T; }

        unsigned long long key =
            ((unsigned long long)__float_as_uint(m) << 32) |
            (unsigned)(~(unsigned)mi);
#pragma unroll
        for (int o = 16; o > 0; o >>= 1) {
            unsigned long long other = __shfl_down_sync(0xffffffffu, key, o);
            if (other > key) key = other;
        }
        if (lane == 0) skey[w] = key;
        __syncthreads();                          /* the ONLY intra barrier */

        if (w == 0) {
            unsigned long long v = (lane < 16) ? skey[lane] : 0ull;
#pragma unroll
            for (int o = 8; o > 0; o >>= 1) {
                unsigned long long other = __shfl_down_sync(0xffffffffu, v, o);
                if (other > v) v = other;
            }
            if (lane == 0) {
                const unsigned myslot = slots_a + (unsigned)(p*FPS_CTAS + rank)*8u;
#pragma unroll
                for (int r = 0; r < FPS_CTAS; r++) st_cluster_u64(myslot, r, v);
#pragma unroll
                for (int r = 0; r < FPS_CTAS; r++) mbar_arrive_cluster(mbar_a, r);
            }
        }

        mbar_wait_cluster(mbar_a, ph);
        ph ^= 1u;

        unsigned long long w0 = slots[p][0], w1 = slots[p][1];
        unsigned long long w2 = slots[p][2], w3 = slots[p][3];
        unsigned long long win = w0 > w1 ? w0 : w1;
        unsigned long long w23 = w2 > w3 ? w2 : w3;
        if (w23 > win) win = w23;

        last = (int)(~(unsigned)win & 0x7fffffffu);
        if (rank == 0 && t == 0) g_fps_idx[b*M + s] = last;
    }
    cluster_sync_all();                   /* no early exit under peers' stores */
}

/* ------------------------------------------------------------------ */
/* Ball query: one warp per center. First K in-ball points by index   */
/* via ballot + prefix popcount, early exit. Also emits pos_s/batch_s.*/
/* ------------------------------------------------------------------ */
__global__ void __launch_bounds__(256) ballquery_kernel(float* __restrict__ out) {
    const int w    = (blockIdx.x * 256 + threadIdx.x) >> 5;
    const int lane = threadIdx.x & 31;
    if (w >= NC) return;
    const int b = w >> 11;                 /* M = 2048 */

    const float* px = g_px + b*N;
    const float* py = g_py + b*N;
    const float* pz = g_pz + b*N;

    const int ci = g_fps_idx[w];
    const float cx = px[ci], cy = py[ci], cz = pz[ci];

    if (lane == 0) {
        out[P_OFF + 3*w + 0] = cx;
        out[P_OFF + 3*w + 1] = cy;
        out[P_OFF + 3*w + 2] = cz;
        out[BA_OFF + w]      = (float)b;   /* batch[b,n] == b */
    }

    int* nb = g_nbr + w*K;
    int cnt = 0;
    for (int base = 0; base < N; base += 32) {
        int n = base + lane;
        float dx = __fadd_rn(px[n], -cx);
        float dy = __fadd_rn(py[n], -cy);
        float dz = __fadd_rn(pz[n], -cz);
        float d  = __fadd_rn(__fadd_rn(__fmul_rn(dx,dx), __fmul_rn(dy,dy)),
                             __fmul_rn(dz,dz));
        bool in = (d <= 0.04f);            /* float32(0.04) == jnp's R*R cast  */
        unsigned msk = __ballot_sync(0xFFFFFFFFu, in);
        if (in) {
            int slot = cnt + __popc(msk & ((1u << lane) - 1u));
            if (slot < K) nb[slot] = n;
        }
        cnt += __popc(msk);
        if (cnt >= K) break;
    }
    int nv = cnt < K ? cnt : K;            /* >=1: center is in its own ball */
    for (int s2 = nv + lane; s2 < K; s2 += 32) nb[s2] = 0;  /* safe gather idx */
    if (lane == 0) g_nvalid[w] = nv;
}

/* ------------------------------------------------------------------ */
/* Fused gather + MLP(16->64->128) + masked max.  (R4 proven version) */
/* ------------------------------------------------------------------ */
__global__ void __launch_bounds__(128, 2) mlp_kernel(
    const float* __restrict__ x,
    const float* __restrict__ W1, const float* __restrict__ b1,
    const float* __restrict__ W2, const float* __restrict__ b2,
    float* __restrict__ out)
{
    __shared__ float sW1[16][64];
    __shared__ float sb1[64];
    __shared__ float sh[2][32][68];        /* padded rows, 16B-aligned */
    __shared__ int   s_nv[2];
    __shared__ int   s_nbr[2][32];
    __shared__ float s_cpos[2][3];

    const int t    = threadIdx.x;
    const int g    = t >> 6;               /* which center of the pair   */
    const int tp   = t & 63;               /* channel-pair id (0..63)    */
    const int kk   = (t >> 1) & 31;        /* neighbor for layer 1       */
    const int half = t & 1;                /* 32-channel half in layer 1 */

    for (int i = t; i < 16*64; i += 128) sW1[i >> 6][i & 63] = W1[i];
    if (t < 64) sb1[t] = b1[t];

    float2 w2r[64];
#pragma unroll
    for (int j = 0; j < 64; j++)
        w2r[j] = *(const float2*)(W2 + j*128 + tp*2);
    const float2 b2v = *(const float2*)(b2 + tp*2);

    for (int pair = blockIdx.x; pair < NPAIR; pair += gridDim.x) {
        const int c = pair*2 + g;
        const int b = c >> 11;

        __syncthreads();                   /* protect sh/s_* reuse */
        if (t < 2) {
            int cc = pair*2 + t;
            s_nv[t] = g_nvalid[cc];
            int ci  = g_fps_idx[cc];
            int bb  = cc >> 11;
            s_cpos[t][0] = g_px[bb*N + ci];
            s_cpos[t][1] = g_py[bb*N + ci];
            s_cpos[t][2] = g_pz[bb*N + ci];
        }
        if (t < 64) {
            int cc = pair*2 + (t >> 5);
            s_nbr[t >> 5][t & 31] = g_nbr[cc*K + (t & 31)];
        }
        __syncthreads();

        /* ---------- layer 1: feat(16) @ W1 -> relu -> sh ---------- */
        const int n  = s_nbr[g][kk];
        const int bn = b*N + n;
        float feat[16];
        const float* xr = x + (size_t)bn * D_INF;
#pragma unroll
        for (int j = 0; j < D_INF; j++) feat[j] = xr[j];
        feat[13] = g_px[bn] - s_cpos[g][0];
        feat[14] = g_py[bn] - s_cpos[g][1];
        feat[15] = g_pz[bn] - s_cpos[g][2];

#pragma unroll
        for (int ph = 0; ph < 2; ph++) {
            const int cbase = half*32 + ph*16;
            float hacc[16];
#pragma unroll
            for (int c2 = 0; c2 < 16; c2++) hacc[c2] = sb1[cbase + c2];
#pragma unroll
            for (int j = 0; j < 16; j++) {
                float f = feat[j];
#pragma unroll
                for (int c2 = 0; c2 < 16; c2++)
                    hacc[c2] = fmaf(f, sW1[j][cbase + c2], hacc[c2]);
            }
#pragma unroll
            for (int c2 = 0; c2 < 16; c2 += 4) {
                float4 v;
                v.x = fmaxf(hacc[c2+0], 0.f);
                v.y = fmaxf(hacc[c2+1], 0.f);
                v.z = fmaxf(hacc[c2+2], 0.f);
                v.w = fmaxf(hacc[c2+3], 0.f);
                *(float4*)&sh[g][kk][cbase + c2] = v;
            }
        }
        __syncthreads();

        /* ---------- layer 2: h @ W2 -> max over valid k -> relu ---- */
        const int nv = s_nv[g];
        float m0 = -3.4e38f, m1 = -3.4e38f;
        for (int k = 0; k < nv; k++) {
            const float* hr = sh[g][k];
            float d0a = 0.f, d0b = 0.f, d1a = 0.f, d1b = 0.f;
#pragma unroll
            for (int j = 0; j < 64; j += 4) {
                float4 hv = *(const float4*)(hr + j);
                d0a = fmaf(hv.x, w2r[j+0].x, d0a); d1a = fmaf(hv.x, w2r[j+0].y, d1a);
                d0b = fmaf(hv.y, w2r[j+1].x, d0b); d1b = fmaf(hv.y, w2r[j+1].y, d1b);
                d0a = fmaf(hv.z, w2r[j+2].x, d0a); d1a = fmaf(hv.z, w2r[j+2].y, d1a);
                d0b = fmaf(hv.w, w2r[j+3].x, d0b); d1b = fmaf(hv.w, w2r[j+3].y, d1b);
            }
            m0 = fmaxf(m0, d0a + d0b);
            m1 = fmaxf(m1, d1a + d1b);
        }
        /* relu(max_k(dot)+b2) == max_k(relu(dot+b2)) since relu monotone,
           and at least one valid neighbor always exists */
        float2 o;
        o.x = fmaxf(m0 + b2v.x, 0.f);
        o.y = fmaxf(m1 + b2v.y, 0.f);
        *(float2*)(out + X_OFF + (size_t)c*128 + tp*2) = o;
    }
}

/* ------------------------------------------------------------------ */
extern "C" void kernel_launch(void* const* d_in, const int* in_sizes, int n_in,
                              void* d_out, int out_size) {
    const float* x   = (const float*)d_in[0];
    const float* pos = (const float*)d_in[1];
    /* d_in[2] = batch (int32), values are just the batch index: unused */
    const float* W1  = (const float*)d_in[3];
    const float* b1  = (const float*)d_in[4];
    const float* W2  = (const float*)d_in[5];
    const float* b2  = (const float*)d_in[6];
    float* out = (float*)d_out;

    soa_kernel<<<(B*N + 255)/256, 256>>>(pos);

    {   /* cluster launch: 8 clusters x 4 CTAs */
        cudaLaunchConfig_t cfg = {};
        cfg.gridDim  = dim3(B * FPS_CTAS, 1, 1);
        cfg.blockDim = dim3(FPS_T, 1, 1);
        cfg.dynamicSmemBytes = 0;
        cfg.stream = 0;
        cudaLaunchAttribute attr[1];
        attr[0].id = cudaLaunchAttributeClusterDimension;
        attr[0].val.clusterDim.x = FPS_CTAS;
        attr[0].val.clusterDim.y = 1;
        attr[0].val.clusterDim.z = 1;
        cfg.attrs = attr;
        cfg.numAttrs = 1;
        cudaLaunchKernelEx(&cfg, fps_kernel);
    }

    ballquery_kernel<<<(NC*32)/256, 256>>>(out);
    mlp_kernel<<<304, 128>>>(x, W1, b1, W2, b2, out);
}